// round 15
// baseline (speedup 1.0000x reference)
#include <cuda_runtime.h>
#include <cuda_fp16.h>

#define BB 8
#define LL 1024
#define DD 1024
#define HH 4
#define DH 256
#define GW 2047
#define GP 2048

typedef unsigned int u32;

// ---------------- device scratch ----------------
__device__ __half g_xh[BB*LL*DD], g_xl[BB*LL*DD];
__device__ __half g_wqh[DD*DD], g_wvh[DD*DD], g_wph[DD*DD];
__device__ __half g_gh[HH*DH*GP];
__device__ __half g_qh[BB*LL*DD], g_ql[BB*LL*DD];
__device__ __half g_vh[BB*LL*DD];
__device__ __half g_ath[BB*LL*DD], g_atl[BB*LL*DD];
__device__ float g_wfull[(size_t)BB*HH*LL*GP];
__device__ __half g_Wh[(size_t)BB*HH*LL*LL], g_Wl[(size_t)BB*HH*LL*LL];
__device__ float g_rs[BB*HH*LL];

// ---------------- helpers ----------------
__device__ __forceinline__ u32 smaddr(const void* p){
    return (u32)__cvta_generic_to_shared(p);
}
__device__ __forceinline__ void ldsm4(u32* r, u32 a){
    asm volatile("ldmatrix.sync.aligned.m8n8.x4.shared.b16 {%0,%1,%2,%3},[%4];"
        :"=r"(r[0]),"=r"(r[1]),"=r"(r[2]),"=r"(r[3]):"r"(a));
}
__device__ __forceinline__ void ldsm4t(u32* r, u32 a){
    asm volatile("ldmatrix.sync.aligned.m8n8.x4.trans.shared.b16 {%0,%1,%2,%3},[%4];"
        :"=r"(r[0]),"=r"(r[1]),"=r"(r[2]),"=r"(r[3]):"r"(a));
}
__device__ __forceinline__ void mma_f16(float* c, const u32* a, const u32* b){
    asm volatile("mma.sync.aligned.m16n8k16.row.col.f32.f16.f16.f32 "
        "{%0,%1,%2,%3},{%4,%5,%6,%7},{%8,%9},{%0,%1,%2,%3};"
        :"+f"(c[0]),"+f"(c[1]),"+f"(c[2]),"+f"(c[3])
        :"r"(a[0]),"r"(a[1]),"r"(a[2]),"r"(a[3]),"r"(b[0]),"r"(b[1]));
}
__device__ __forceinline__ void st_pair(__half* H, __half* L, size_t off, float v0, float v1){
    __half h0=__float2half_rn(v0), h1=__float2half_rn(v1);
    __half2 hh; hh.x=h0; hh.y=h1;
    __half2 ll;
    ll.x=__float2half_rn(v0-__half2float(h0));
    ll.y=__float2half_rn(v1-__half2float(h1));
    *(__half2*)(H+off)=hh; *(__half2*)(L+off)=ll;
}

// ---------------- converts ----------------
__global__ void conv_pair(const float* __restrict__ in, __half* __restrict__ hi,
                          __half* __restrict__ lo, int n){
    int i = blockIdx.x*256 + threadIdx.x;
    if (i < n){
        float v = in[i];
        __half h = __float2half_rn(v);
        hi[i]=h; lo[i]=__float2half_rn(v-__half2float(h));
    }
}
__global__ void conv_hi(const float* __restrict__ in, __half* __restrict__ hi, int n){
    int i = blockIdx.x*256 + threadIdx.x;
    if (i < n) hi[i]=__float2half_rn(in[i]);
}
__global__ void conv_gen_k(const float* __restrict__ gen){
    int idx = blockIdx.x*256 + threadIdx.x;
    int j = idx & (GP-1);
    int r = idx >> 11;
    float v = (j < GW) ? gen[(size_t)r*GW + j] : 0.f;
    g_gh[idx]=__float2half_rn(v);
}

// ---------------------------------------------------------------------------
// NT GEMM (projections): C[8192,1024] = A @ B^T. Block 256x128, 8 warps,
// warp tile 64x64, fp16 2-term (A hi/lo), BK=16 double-buffered.
// emit: 0 = fp32 to Cf, 1 = pair to Chg/Clg, 2 = hi-only to Chg.
// ---------------------------------------------------------------------------
#define NT2_SMEM 61440

__global__ __launch_bounds__(256) void mma_nt2(
    const __half* __restrict__ Ahg, const __half* __restrict__ Alg,
    const __half* __restrict__ Bhg,
    float* __restrict__ Cf, __half* __restrict__ Chg, __half* __restrict__ Clg,
    int emit)
{
    extern __shared__ __align__(16) char dsm[];
    __half* sAh = (__half*)dsm;                   // [2][256][24]
    __half* sAl = (__half*)(dsm + 24576);
    __half* sB  = (__half*)(dsm + 49152);         // [2][128][24]
    const int tid=threadIdx.x, lane=tid&31, wid=tid>>5;
    const int wm=wid>>1, wn=wid&1;
    const int m0=blockIdx.y*256, n0=blockIdx.x*128;

    const int lr=tid>>1, lc8=(tid&1)*8;
    const __half* Ah0=Ahg+(size_t)(m0+lr)*DD+lc8;
    const __half* Ah1=Ahg+(size_t)(m0+lr+128)*DD+lc8;
    const __half* Al0=Alg+(size_t)(m0+lr)*DD+lc8;
    const __half* Al1=Alg+(size_t)(m0+lr+128)*DD+lc8;
    const __half* Bp =Bhg+(size_t)(n0+lr)*DD+lc8;

    float acc[4][8][4];
#pragma unroll
    for(int i=0;i<4;i++)
#pragma unroll
    for(int j=0;j<8;j++)
#pragma unroll
    for(int k2=0;k2<4;k2++) acc[i][j][k2]=0.f;

    uint4 ph0=*(const uint4*)Ah0, ph1=*(const uint4*)Ah1;
    uint4 pl0=*(const uint4*)Al0, pl1=*(const uint4*)Al1;
    uint4 pb =*(const uint4*)Bp;
    *(uint4*)&sAh[lr*24+lc8]        = ph0;
    *(uint4*)&sAh[(lr+128)*24+lc8]  = ph1;
    *(uint4*)&sAl[lr*24+lc8]        = pl0;
    *(uint4*)&sAl[(lr+128)*24+lc8]  = pl1;
    *(uint4*)&sB [lr*24+lc8]        = pb;
    __syncthreads();

    const int nst = DD/16;
    int buf = 0;
    const int g=lane>>3;
    const int arow=((g&1)<<3)+(lane&7), acol=(g>>1)<<3;
    const int brow=((g>>1)<<3)+(lane&7), bcol=(g&1)<<3;
    const int aoff = 256*24, boff = 128*24;

    for(int it=0; it<nst; it++){
        if(it+1<nst){
            const int kb=(it+1)*16;
            ph0=*(const uint4*)(Ah0+kb); ph1=*(const uint4*)(Ah1+kb);
            pl0=*(const uint4*)(Al0+kb); pl1=*(const uint4*)(Al1+kb);
            pb =*(const uint4*)(Bp +kb);
        }
        u32 afh[4][4], afl[4][4];
#pragma unroll
        for(int mt=0;mt<4;mt++){
            ldsm4(afh[mt], smaddr(&sAh[buf*aoff+(wm*64+mt*16+arow)*24+acol]));
            ldsm4(afl[mt], smaddr(&sAl[buf*aoff+(wm*64+mt*16+arow)*24+acol]));
        }
        u32 bfh[4][4];
#pragma unroll
        for(int np=0;np<4;np++)
            ldsm4(bfh[np], smaddr(&sB[buf*boff+(wn*64+np*16+brow)*24+bcol]));
#pragma unroll
        for(int mt=0;mt<4;mt++)
#pragma unroll
        for(int np=0;np<4;np++)
#pragma unroll
        for(int hf=0;hf<2;hf++){
            int nt=np*2+hf;
            mma_f16(acc[mt][nt], afh[mt], &bfh[np][hf*2]);
            mma_f16(acc[mt][nt], afl[mt], &bfh[np][hf*2]);
        }
        if(it+1<nst){
            buf^=1;
            *(uint4*)&sAh[buf*aoff+lr*24+lc8]       = ph0;
            *(uint4*)&sAh[buf*aoff+(lr+128)*24+lc8] = ph1;
            *(uint4*)&sAl[buf*aoff+lr*24+lc8]       = pl0;
            *(uint4*)&sAl[buf*aoff+(lr+128)*24+lc8] = pl1;
            *(uint4*)&sB [buf*boff+lr*24+lc8]       = pb;
            __syncthreads();
        }
    }
#pragma unroll
    for(int mt=0;mt<4;mt++)
#pragma unroll
    for(int nt=0;nt<8;nt++){
        int r=m0+wm*64+mt*16+(lane>>2);
        int c=n0+wn*64+nt*8+((lane&3)<<1);
        float* a4=acc[mt][nt];
        if(emit==1){
            st_pair(Chg,Clg,(size_t)r*DD+c,a4[0],a4[1]);
            st_pair(Chg,Clg,(size_t)(r+8)*DD+c,a4[2],a4[3]);
        } else if(emit==2){
            __half2 h0; h0.x=__float2half_rn(a4[0]); h0.y=__float2half_rn(a4[1]);
            __half2 h1; h1.x=__float2half_rn(a4[2]); h1.y=__float2half_rn(a4[3]);
            *(__half2*)(Chg+(size_t)r*DD+c)=h0;
            *(__half2*)(Chg+(size_t)(r+8)*DD+c)=h1;
        } else {
            *(float2*)(Cf+(size_t)r*DD+c)=make_float2(a4[0],a4[1]);
            *(float2*)(Cf+(size_t)(r+8)*DD+c)=make_float2(a4[2],a4[3]);
        }
    }
}

// ---------------------------------------------------------------------------
// Score GEMM: wfull[bh,l,j] = sum_k q[b,l,h*DH+k]*gen[h,k,j].
// Block 256(l)x128(j), 8 warps, 64x64 warp tile, BK=16, K=DH=256.
// Band: tile live iff 641 <= l0+j0 <= 2046.
// smem: sAh/sAl [2][256][24], sB [2][16][136] (gen rows, trans ldsm).
// ---------------------------------------------------------------------------
#define SC_SMEM (49152 + 8704)

__global__ __launch_bounds__(256) void mma_score(){
    const int l0=blockIdx.y*256, j0=blockIdx.x*128;
    if (l0 + j0 < 641 || l0 + j0 > 2046) return;
    extern __shared__ __align__(16) char dsm[];
    __half* sAh = (__half*)dsm;                   // [2][256][24]
    __half* sAl = (__half*)(dsm + 24576);
    __half* sB  = (__half*)(dsm + 49152);         // [2][16][136]
    const int tid=threadIdx.x, lane=tid&31, wid=tid>>5;
    const int wm=wid>>1, wn=wid&1;
    const int bh=blockIdx.z, b=bh>>2, h=bh&3;

    const int lr=tid>>1, lc8=(tid&1)*8;
    const __half* Ah0=g_qh+(size_t)(b*LL+l0+lr)*DD+h*DH+lc8;
    const __half* Ah1=g_qh+(size_t)(b*LL+l0+lr+128)*DD+h*DH+lc8;
    const __half* Al0=g_ql+(size_t)(b*LL+l0+lr)*DD+h*DH+lc8;
    const __half* Al1=g_ql+(size_t)(b*LL+l0+lr+128)*DD+h*DH+lc8;
    const int vbr=tid>>4, vbc=(tid&15)<<3;
    const __half* Bp=g_gh+(size_t)(h*DH+vbr)*GP+j0+vbc;

    float acc[4][8][4];
#pragma unroll
    for(int i=0;i<4;i++)
#pragma unroll
    for(int j=0;j<8;j++)
#pragma unroll
    for(int k2=0;k2<4;k2++) acc[i][j][k2]=0.f;

    uint4 ph0=*(const uint4*)Ah0, ph1=*(const uint4*)Ah1;
    uint4 pl0=*(const uint4*)Al0, pl1=*(const uint4*)Al1;
    uint4 pb =*(const uint4*)Bp;
    *(uint4*)&sAh[lr*24+lc8]        = ph0;
    *(uint4*)&sAh[(lr+128)*24+lc8]  = ph1;
    *(uint4*)&sAl[lr*24+lc8]        = pl0;
    *(uint4*)&sAl[(lr+128)*24+lc8]  = pl1;
    *(uint4*)&sB [vbr*136+vbc]      = pb;
    __syncthreads();

    const int nst = DH/16;   // 16
    int buf = 0;
    const int g=lane>>3;
    const int arow=((g&1)<<3)+(lane&7), acol=(g>>1)<<3;
    const int tbrow=((g&1)<<3)+(lane&7), tbcoff=(g>>1)<<3;
    const int aoff = 256*24, boff = 16*136;

    for(int it=0; it<nst; it++){
        if(it+1<nst){
            const int kb=(it+1)*16;
            ph0=*(const uint4*)(Ah0+kb); ph1=*(const uint4*)(Ah1+kb);
            pl0=*(const uint4*)(Al0+kb); pl1=*(const uint4*)(Al1+kb);
            pb =*(const uint4*)(Bp + (size_t)kb*GP);
        }
        u32 afh[4][4], afl[4][4];
#pragma unroll
        for(int mt=0;mt<4;mt++){
            ldsm4(afh[mt], smaddr(&sAh[buf*aoff+(wm*64+mt*16+arow)*24+acol]));
            ldsm4(afl[mt], smaddr(&sAl[buf*aoff+(wm*64+mt*16+arow)*24+acol]));
        }
        u32 bfh[4][4];
#pragma unroll
        for(int np=0;np<4;np++)
            ldsm4t(bfh[np], smaddr(&sB[buf*boff+tbrow*136+wn*64+np*16+tbcoff]));
#pragma unroll
        for(int mt=0;mt<4;mt++)
#pragma unroll
        for(int np=0;np<4;np++)
#pragma unroll
        for(int hf=0;hf<2;hf++){
            int nt=np*2+hf;
            mma_f16(acc[mt][nt], afh[mt], &bfh[np][hf*2]);
            mma_f16(acc[mt][nt], afl[mt], &bfh[np][hf*2]);
        }
        if(it+1<nst){
            buf^=1;
            *(uint4*)&sAh[buf*aoff+lr*24+lc8]       = ph0;
            *(uint4*)&sAh[buf*aoff+(lr+128)*24+lc8] = ph1;
            *(uint4*)&sAl[buf*aoff+lr*24+lc8]       = pl0;
            *(uint4*)&sAl[buf*aoff+(lr+128)*24+lc8] = pl1;
            *(uint4*)&sB [buf*boff+vbr*136+vbc]     = pb;
            __syncthreads();
        }
    }
    float* dst=g_wfull+(size_t)bh*LL*GP;
#pragma unroll
    for(int mt=0;mt<4;mt++)
#pragma unroll
    for(int nt=0;nt<8;nt++){
        int r=l0+wm*64+mt*16+(lane>>2);
        int c=j0+wn*64+nt*8+((lane&3)<<1);
        float* a4=acc[mt][nt];
        *(float2*)(dst+(size_t)r*GP+c)=make_float2(a4[0],a4[1]);
        *(float2*)(dst+(size_t)(r+8)*GP+c)=make_float2(a4[2],a4[3]);
    }
}

// ---------------------------------------------------------------------------
// Fused Toeplitz gather + cumsum + relu + mask; W emitted as fp16 pair.
// ---------------------------------------------------------------------------
__global__ __launch_bounds__(256) void cumsum_fuse(){
    const int bh=blockIdx.y;
    const int i=blockIdx.x*256+threadIdx.x;
    const float* src=g_wfull+(size_t)bh*LL*GP+1023+i;
    __half* wh=g_Wh+(size_t)bh*LL*LL+i;
    __half* wl=g_Wl+(size_t)bh*LL*LL+i;
    float acc=0.f;
    for(int l=0;l<LL;l+=8){
        float vb[8];
#pragma unroll
        for(int u=0;u<8;u++) vb[u]=src[(size_t)(l+u)*2047];
#pragma unroll
        for(int u=0;u<8;u++){
            acc+=vb[u];
            float m=(i<=l+u)?fmaxf(acc,0.f):0.f;
            __half hh=__float2half_rn(m);
            wh[(size_t)(l+u)*LL]=hh;
            wl[(size_t)(l+u)*LL]=__float2half_rn(m-__half2float(hh));
        }
    }
}

// ---------------------------------------------------------------------------
__global__ __launch_bounds__(256) void rowsum_k(){
    const int bh=blockIdx.y, l=blockIdx.x;
    const __half* wh=g_Wh+(size_t)(bh*LL+l)*LL;
    const __half* wl=g_Wl+(size_t)(bh*LL+l)*LL;
    float s=0.f;
    for(int i=threadIdx.x;i<=l;i+=256)
        s+=__half2float(wh[i])+__half2float(wl[i]);
#pragma unroll
    for(int o=16;o>0;o>>=1) s+=__shfl_xor_sync(0xffffffffu,s,o);
    __shared__ float red[8];
    if((threadIdx.x&31)==0) red[threadIdx.x>>5]=s;
    __syncthreads();
    if(threadIdx.x<8){
        s=red[threadIdx.x];
#pragma unroll
        for(int o=4;o>0;o>>=1) s+=__shfl_xor_sync(0xffu,s,o);
        if(threadIdx.x==0) g_rs[bh*LL+l]=s;
    }
}

// ---------------------------------------------------------------------------
// AV GEMM: attn = normalize(W) @ v (causal).
// Block 256(l)x128(n), 8 warps, 64x64 warp tile, BK=16, causal K bound.
// ---------------------------------------------------------------------------
__global__ __launch_bounds__(256) void mma_av(){
    extern __shared__ __align__(16) char dsm[];
    __half* sAh = (__half*)dsm;                   // [2][256][24]
    __half* sAl = (__half*)(dsm + 24576);
    __half* sB  = (__half*)(dsm + 49152);         // [2][16][136]
    const int tid=threadIdx.x, lane=tid&31, wid=tid>>5;
    const int wm=wid>>1, wn=wid&1;
    const int bh=blockIdx.z, b=bh>>2, h=bh&3;
    const int l0=blockIdx.y*256, n0=blockIdx.x*128;

    const int lr=tid>>1, lc8=(tid&1)*8;
    const __half* Ah0=g_Wh+(size_t)(bh*LL+l0+lr)*LL+lc8;
    const __half* Ah1=g_Wh+(size_t)(bh*LL+l0+lr+128)*LL+lc8;
    const __half* Al0=g_Wl+(size_t)(bh*LL+l0+lr)*LL+lc8;
    const __half* Al1=g_Wl+(size_t)(bh*LL+l0+lr+128)*LL+lc8;
    const int vbr=tid>>4, vbc=(tid&15)<<3;
    const __half* Bp=g_vh+(size_t)(b*LL+vbr)*DD+h*DH+n0+vbc;

    float acc[4][8][4];
#pragma unroll
    for(int i=0;i<4;i++)
#pragma unroll
    for(int j=0;j<8;j++)
#pragma unroll
    for(int k2=0;k2<4;k2++) acc[i][j][k2]=0.f;

    uint4 ph0=*(const uint4*)Ah0, ph1=*(const uint4*)Ah1;
    uint4 pl0=*(const uint4*)Al0, pl1=*(const uint4*)Al1;
    uint4 pb =*(const uint4*)Bp;
    *(uint4*)&sAh[lr*24+lc8]        = ph0;
    *(uint4*)&sAh[(lr+128)*24+lc8]  = ph1;
    *(uint4*)&sAl[lr*24+lc8]        = pl0;
    *(uint4*)&sAl[(lr+128)*24+lc8]  = pl1;
    *(uint4*)&sB [vbr*136+vbc]      = pb;
    __syncthreads();

    const int nst = (l0+256)/16;
    int buf = 0;
    const int g=lane>>3;
    const int arow=((g&1)<<3)+(lane&7), acol=(g>>1)<<3;
    const int tbrow=((g&1)<<3)+(lane&7), tbcoff=(g>>1)<<3;
    const int aoff = 256*24, boff = 16*136;

    for(int it=0; it<nst; it++){
        if(it+1<nst){
            const int kb=(it+1)*16;
            ph0=*(const uint4*)(Ah0+kb); ph1=*(const uint4*)(Ah1+kb);
            pl0=*(const uint4*)(Al0+kb); pl1=*(const uint4*)(Al1+kb);
            pb =*(const uint4*)(Bp + (size_t)kb*DD);
        }
        u32 afh[4][4], afl[4][4];
#pragma unroll
        for(int mt=0;mt<4;mt++){
            ldsm4(afh[mt], smaddr(&sAh[buf*aoff+(wm*64+mt*16+arow)*24+acol]));
            ldsm4(afl[mt], smaddr(&sAl[buf*aoff+(wm*64+mt*16+arow)*24+acol]));
        }
        u32 bfh[4][4];
#pragma unroll
        for(int np=0;np<4;np++)
            ldsm4t(bfh[np], smaddr(&sB[buf*boff+tbrow*136+wn*64+np*16+tbcoff]));
#pragma unroll
        for(int mt=0;mt<4;mt++)
#pragma unroll
        for(int np=0;np<4;np++)
#pragma unroll
        for(int hf=0;hf<2;hf++){
            int nt=np*2+hf;
            mma_f16(acc[mt][nt], afh[mt], &bfh[np][hf*2]);
            mma_f16(acc[mt][nt], afl[mt], &bfh[np][hf*2]);
        }
        if(it+1<nst){
            buf^=1;
            *(uint4*)&sAh[buf*aoff+lr*24+lc8]       = ph0;
            *(uint4*)&sAh[buf*aoff+(lr+128)*24+lc8] = ph1;
            *(uint4*)&sAl[buf*aoff+lr*24+lc8]       = pl0;
            *(uint4*)&sAl[buf*aoff+(lr+128)*24+lc8] = pl1;
            *(uint4*)&sB [buf*boff+vbr*136+vbc]     = pb;
            __syncthreads();
        }
    }
#pragma unroll
    for(int mt=0;mt<4;mt++)
#pragma unroll
    for(int nt=0;nt<8;nt++){
        int r=l0+wm*64+mt*16+(lane>>2);
        int cD=h*DH+n0+wn*64+nt*8+((lane&3)<<1);
        float s0=1.f/(g_rs[bh*LL+r]+1e-8f);
        float s1=1.f/(g_rs[bh*LL+r+8]+1e-8f);
        float* a4=acc[mt][nt];
        st_pair(g_ath,g_atl,(size_t)(b*LL+r)*DD+cD,a4[0]*s0,a4[1]*s0);
        st_pair(g_ath,g_atl,(size_t)(b*LL+r+8)*DD+cD,a4[2]*s1,a4[3]*s1);
    }
}

// ---------------------------------------------------------------------------
extern "C" void kernel_launch(void* const* d_in, const int* in_sizes, int n_in,
                              void* d_out, int out_size) {
    const float* x   = (const float*)d_in[0];
    const float* gen = (const float*)d_in[1];
    const float* Wq  = (const float*)d_in[2];
    const float* Wv  = (const float*)d_in[3];
    const float* Wp  = (const float*)d_in[4];
    float* out = (float*)d_out;

    __half *xh,*xl,*wqh,*wvh,*wph,*qh,*ql,*vh,*ath,*atl;
    cudaGetSymbolAddress((void**)&xh,  g_xh);  cudaGetSymbolAddress((void**)&xl,  g_xl);
    cudaGetSymbolAddress((void**)&wqh, g_wqh);
    cudaGetSymbolAddress((void**)&wvh, g_wvh);
    cudaGetSymbolAddress((void**)&wph, g_wph);
    cudaGetSymbolAddress((void**)&qh,  g_qh);  cudaGetSymbolAddress((void**)&ql,  g_ql);
    cudaGetSymbolAddress((void**)&vh,  g_vh);
    cudaGetSymbolAddress((void**)&ath, g_ath); cudaGetSymbolAddress((void**)&atl, g_atl);

    cudaFuncSetAttribute(mma_nt2, cudaFuncAttributeMaxDynamicSharedMemorySize, NT2_SMEM);
    cudaFuncSetAttribute(mma_score, cudaFuncAttributeMaxDynamicSharedMemorySize, SC_SMEM);
    cudaFuncSetAttribute(mma_av, cudaFuncAttributeMaxDynamicSharedMemorySize, SC_SMEM);

    conv_pair<<<(BB*LL*DD)/256,256>>>(x, xh, xl, BB*LL*DD);
    conv_hi<<<(DD*DD)/256,256>>>(Wq, wqh, DD*DD);
    conv_hi<<<(DD*DD)/256,256>>>(Wv, wvh, DD*DD);
    conv_hi<<<(DD*DD)/256,256>>>(Wp, wph, DD*DD);
    conv_gen_k<<<(HH*DH*GP)/256,256>>>(gen);

    dim3 gproj(DD/128, BB*LL/256);   // (8, 32)
    mma_nt2<<<gproj, 256, NT2_SMEM>>>(xh, xl, wqh, nullptr, qh, ql, 1);
    mma_nt2<<<gproj, 256, NT2_SMEM>>>(xh, xl, wvh, nullptr, vh, nullptr, 2);

    mma_score<<<dim3(GP/128, LL/256, BB*HH), 256, SC_SMEM>>>();
    cumsum_fuse<<<dim3(LL/256, BB*HH),256>>>();
    rowsum_k<<<dim3(LL, BB*HH),256>>>();
    mma_av<<<dim3(DH/128, LL/256, BB*HH), 256, SC_SMEM>>>();

    mma_nt2<<<gproj, 256, NT2_SMEM>>>(ath, atl, wph, out, nullptr, nullptr, 0);
}

// round 16
// speedup vs baseline: 1.0186x; 1.0186x over previous
#include <cuda_runtime.h>
#include <cuda_fp16.h>

#define BB 8
#define LL 1024
#define DD 1024
#define HH 4
#define DH 256
#define GW 2047
#define GP 2048

typedef unsigned int u32;

// ---------------- device scratch ----------------
__device__ __half g_xh[BB*LL*DD], g_xl[BB*LL*DD];
__device__ __half g_wqh[DD*DD], g_wvh[DD*DD], g_wph[DD*DD];
__device__ __half g_gh[HH*DH*GP];
__device__ __half g_qh[BB*LL*DD], g_ql[BB*LL*DD];
__device__ __half g_vh[BB*LL*DD];
__device__ __half g_ath[BB*LL*DD], g_atl[BB*LL*DD];
__device__ float g_wfull[(size_t)BB*HH*LL*GP];
__device__ __half g_Wh[(size_t)BB*HH*LL*LL], g_Wl[(size_t)BB*HH*LL*LL];
__device__ float g_rs[BB*HH*LL];

// ---------------- helpers ----------------
__device__ __forceinline__ u32 smaddr(const void* p){
    return (u32)__cvta_generic_to_shared(p);
}
__device__ __forceinline__ void ldsm4(u32* r, u32 a){
    asm volatile("ldmatrix.sync.aligned.m8n8.x4.shared.b16 {%0,%1,%2,%3},[%4];"
        :"=r"(r[0]),"=r"(r[1]),"=r"(r[2]),"=r"(r[3]):"r"(a));
}
__device__ __forceinline__ void ldsm4t(u32* r, u32 a){
    asm volatile("ldmatrix.sync.aligned.m8n8.x4.trans.shared.b16 {%0,%1,%2,%3},[%4];"
        :"=r"(r[0]),"=r"(r[1]),"=r"(r[2]),"=r"(r[3]):"r"(a));
}
__device__ __forceinline__ void mma_f16(float* c, const u32* a, const u32* b){
    asm volatile("mma.sync.aligned.m16n8k16.row.col.f32.f16.f16.f32 "
        "{%0,%1,%2,%3},{%4,%5,%6,%7},{%8,%9},{%0,%1,%2,%3};"
        :"+f"(c[0]),"+f"(c[1]),"+f"(c[2]),"+f"(c[3])
        :"r"(a[0]),"r"(a[1]),"r"(a[2]),"r"(a[3]),"r"(b[0]),"r"(b[1]));
}
__device__ __forceinline__ void st_pair(__half* H, __half* L, size_t off, float v0, float v1){
    __half h0=__float2half_rn(v0), h1=__float2half_rn(v1);
    __half2 hh; hh.x=h0; hh.y=h1;
    __half2 ll;
    ll.x=__float2half_rn(v0-__half2float(h0));
    ll.y=__float2half_rn(v1-__half2float(h1));
    *(__half2*)(H+off)=hh; *(__half2*)(L+off)=ll;
}

// ---------------- fused conversion (x pair, 3 weights hi, gen hi) --------
#define N_XPAIR (BB*LL*DD)                 // 8388608
#define N_W     (DD*DD)                    // 1048576
#define N_GEN   (HH*DH*GP)                 // 2097152
#define N_CONV  (N_XPAIR + 3*N_W + N_GEN)  // 13631488

__global__ void conv_all(const float* __restrict__ x,
                         const float* __restrict__ Wq,
                         const float* __restrict__ Wv,
                         const float* __restrict__ Wp,
                         const float* __restrict__ gen){
    int idx = blockIdx.x*256 + threadIdx.x;
    if (idx < N_XPAIR){
        float v = x[idx];
        __half h = __float2half_rn(v);
        g_xh[idx]=h; g_xl[idx]=__float2half_rn(v-__half2float(h));
        return;
    }
    idx -= N_XPAIR;
    if (idx < N_W){ g_wqh[idx]=__float2half_rn(Wq[idx]); return; }
    idx -= N_W;
    if (idx < N_W){ g_wvh[idx]=__float2half_rn(Wv[idx]); return; }
    idx -= N_W;
    if (idx < N_W){ g_wph[idx]=__float2half_rn(Wp[idx]); return; }
    idx -= N_W;
    if (idx < N_GEN){
        int j = idx & (GP-1), r = idx >> 11;
        float v = (j < GW) ? gen[(size_t)r*GW + j] : 0.f;
        g_gh[idx]=__float2half_rn(v);
    }
}

__global__ void zero_rs(){ g_rs[blockIdx.x*256 + threadIdx.x] = 0.f; }

// ---------------------------------------------------------------------------
// NT GEMM (projections): C[8192,1024] = A @ B^T. Block 256x128, 8 warps,
// warp tile 64x64, fp16 2-term (A hi/lo), BK=16 double-buffered.
// emit: 0 = fp32 to Cf, 1 = pair to Chg/Clg, 2 = hi-only to Chg.
// ---------------------------------------------------------------------------
#define NT2_SMEM 61440

__global__ __launch_bounds__(256) void mma_nt2(
    const __half* __restrict__ Ahg, const __half* __restrict__ Alg,
    const __half* __restrict__ Bhg,
    float* __restrict__ Cf, __half* __restrict__ Chg, __half* __restrict__ Clg,
    int emit)
{
    extern __shared__ __align__(16) char dsm[];
    __half* sAh = (__half*)dsm;                   // [2][256][24]
    __half* sAl = (__half*)(dsm + 24576);
    __half* sB  = (__half*)(dsm + 49152);         // [2][128][24]
    const int tid=threadIdx.x, lane=tid&31, wid=tid>>5;
    const int wm=wid>>1, wn=wid&1;
    const int m0=blockIdx.y*256, n0=blockIdx.x*128;

    const int lr=tid>>1, lc8=(tid&1)*8;
    const __half* Ah0=Ahg+(size_t)(m0+lr)*DD+lc8;
    const __half* Ah1=Ahg+(size_t)(m0+lr+128)*DD+lc8;
    const __half* Al0=Alg+(size_t)(m0+lr)*DD+lc8;
    const __half* Al1=Alg+(size_t)(m0+lr+128)*DD+lc8;
    const __half* Bp =Bhg+(size_t)(n0+lr)*DD+lc8;

    float acc[4][8][4];
#pragma unroll
    for(int i=0;i<4;i++)
#pragma unroll
    for(int j=0;j<8;j++)
#pragma unroll
    for(int k2=0;k2<4;k2++) acc[i][j][k2]=0.f;

    uint4 ph0=*(const uint4*)Ah0, ph1=*(const uint4*)Ah1;
    uint4 pl0=*(const uint4*)Al0, pl1=*(const uint4*)Al1;
    uint4 pb =*(const uint4*)Bp;
    *(uint4*)&sAh[lr*24+lc8]        = ph0;
    *(uint4*)&sAh[(lr+128)*24+lc8]  = ph1;
    *(uint4*)&sAl[lr*24+lc8]        = pl0;
    *(uint4*)&sAl[(lr+128)*24+lc8]  = pl1;
    *(uint4*)&sB [lr*24+lc8]        = pb;
    __syncthreads();

    const int nst = DD/16;
    int buf = 0;
    const int g=lane>>3;
    const int arow=((g&1)<<3)+(lane&7), acol=(g>>1)<<3;
    const int brow=((g>>1)<<3)+(lane&7), bcol=(g&1)<<3;
    const int aoff = 256*24, boff = 128*24;

    for(int it=0; it<nst; it++){
        if(it+1<nst){
            const int kb=(it+1)*16;
            ph0=*(const uint4*)(Ah0+kb); ph1=*(const uint4*)(Ah1+kb);
            pl0=*(const uint4*)(Al0+kb); pl1=*(const uint4*)(Al1+kb);
            pb =*(const uint4*)(Bp +kb);
        }
        u32 afh[4][4], afl[4][4];
#pragma unroll
        for(int mt=0;mt<4;mt++){
            ldsm4(afh[mt], smaddr(&sAh[buf*aoff+(wm*64+mt*16+arow)*24+acol]));
            ldsm4(afl[mt], smaddr(&sAl[buf*aoff+(wm*64+mt*16+arow)*24+acol]));
        }
        u32 bfh[4][4];
#pragma unroll
        for(int np=0;np<4;np++)
            ldsm4(bfh[np], smaddr(&sB[buf*boff+(wn*64+np*16+brow)*24+bcol]));
#pragma unroll
        for(int mt=0;mt<4;mt++)
#pragma unroll
        for(int np=0;np<4;np++)
#pragma unroll
        for(int hf=0;hf<2;hf++){
            int nt=np*2+hf;
            mma_f16(acc[mt][nt], afh[mt], &bfh[np][hf*2]);
            mma_f16(acc[mt][nt], afl[mt], &bfh[np][hf*2]);
        }
        if(it+1<nst){
            buf^=1;
            *(uint4*)&sAh[buf*aoff+lr*24+lc8]       = ph0;
            *(uint4*)&sAh[buf*aoff+(lr+128)*24+lc8] = ph1;
            *(uint4*)&sAl[buf*aoff+lr*24+lc8]       = pl0;
            *(uint4*)&sAl[buf*aoff+(lr+128)*24+lc8] = pl1;
            *(uint4*)&sB [buf*boff+lr*24+lc8]       = pb;
            __syncthreads();
        }
    }
#pragma unroll
    for(int mt=0;mt<4;mt++)
#pragma unroll
    for(int nt=0;nt<8;nt++){
        int r=m0+wm*64+mt*16+(lane>>2);
        int c=n0+wn*64+nt*8+((lane&3)<<1);
        float* a4=acc[mt][nt];
        if(emit==1){
            st_pair(Chg,Clg,(size_t)r*DD+c,a4[0],a4[1]);
            st_pair(Chg,Clg,(size_t)(r+8)*DD+c,a4[2],a4[3]);
        } else if(emit==2){
            __half2 h0; h0.x=__float2half_rn(a4[0]); h0.y=__float2half_rn(a4[1]);
            __half2 h1; h1.x=__float2half_rn(a4[2]); h1.y=__float2half_rn(a4[3]);
            *(__half2*)(Chg+(size_t)r*DD+c)=h0;
            *(__half2*)(Chg+(size_t)(r+8)*DD+c)=h1;
        } else {
            *(float2*)(Cf+(size_t)r*DD+c)=make_float2(a4[0],a4[1]);
            *(float2*)(Cf+(size_t)(r+8)*DD+c)=make_float2(a4[2],a4[3]);
        }
    }
}

// ---------------------------------------------------------------------------
// Score GEMM: wfull[bh,l,j] = sum_k q[b,l,h*DH+k]*gen[h,k,j].
// Block 256(l)x128(j), 8 warps, 64x64 warp tile, BK=16, K=DH=256.
// Band: tile live iff 641 <= l0+j0 <= 2046.
// ---------------------------------------------------------------------------
#define SC_SMEM (49152 + 8704)

__global__ __launch_bounds__(256) void mma_score(){
    const int l0=blockIdx.y*256, j0=blockIdx.x*128;
    if (l0 + j0 < 641 || l0 + j0 > 2046) return;
    extern __shared__ __align__(16) char dsm[];
    __half* sAh = (__half*)dsm;                   // [2][256][24]
    __half* sAl = (__half*)(dsm + 24576);
    __half* sB  = (__half*)(dsm + 49152);         // [2][16][136]
    const int tid=threadIdx.x, lane=tid&31, wid=tid>>5;
    const int wm=wid>>1, wn=wid&1;
    const int bh=blockIdx.z, b=bh>>2, h=bh&3;

    const int lr=tid>>1, lc8=(tid&1)*8;
    const __half* Ah0=g_qh+(size_t)(b*LL+l0+lr)*DD+h*DH+lc8;
    const __half* Ah1=g_qh+(size_t)(b*LL+l0+lr+128)*DD+h*DH+lc8;
    const __half* Al0=g_ql+(size_t)(b*LL+l0+lr)*DD+h*DH+lc8;
    const __half* Al1=g_ql+(size_t)(b*LL+l0+lr+128)*DD+h*DH+lc8;
    const int vbr=tid>>4, vbc=(tid&15)<<3;
    const __half* Bp=g_gh+(size_t)(h*DH+vbr)*GP+j0+vbc;

    float acc[4][8][4];
#pragma unroll
    for(int i=0;i<4;i++)
#pragma unroll
    for(int j=0;j<8;j++)
#pragma unroll
    for(int k2=0;k2<4;k2++) acc[i][j][k2]=0.f;

    uint4 ph0=*(const uint4*)Ah0, ph1=*(const uint4*)Ah1;
    uint4 pl0=*(const uint4*)Al0, pl1=*(const uint4*)Al1;
    uint4 pb =*(const uint4*)Bp;
    *(uint4*)&sAh[lr*24+lc8]        = ph0;
    *(uint4*)&sAh[(lr+128)*24+lc8]  = ph1;
    *(uint4*)&sAl[lr*24+lc8]        = pl0;
    *(uint4*)&sAl[(lr+128)*24+lc8]  = pl1;
    *(uint4*)&sB [vbr*136+vbc]      = pb;
    __syncthreads();

    const int nst = DH/16;
    int buf = 0;
    const int g=lane>>3;
    const int arow=((g&1)<<3)+(lane&7), acol=(g>>1)<<3;
    const int tbrow=((g&1)<<3)+(lane&7), tbcoff=(g>>1)<<3;
    const int aoff = 256*24, boff = 16*136;

    for(int it=0; it<nst; it++){
        if(it+1<nst){
            const int kb=(it+1)*16;
            ph0=*(const uint4*)(Ah0+kb); ph1=*(const uint4*)(Ah1+kb);
            pl0=*(const uint4*)(Al0+kb); pl1=*(const uint4*)(Al1+kb);
            pb =*(const uint4*)(Bp + (size_t)kb*GP);
        }
        u32 afh[4][4], afl[4][4];
#pragma unroll
        for(int mt=0;mt<4;mt++){
            ldsm4(afh[mt], smaddr(&sAh[buf*aoff+(wm*64+mt*16+arow)*24+acol]));
            ldsm4(afl[mt], smaddr(&sAl[buf*aoff+(wm*64+mt*16+arow)*24+acol]));
        }
        u32 bfh[4][4];
#pragma unroll
        for(int np=0;np<4;np++)
            ldsm4t(bfh[np], smaddr(&sB[buf*boff+tbrow*136+wn*64+np*16+tbcoff]));
#pragma unroll
        for(int mt=0;mt<4;mt++)
#pragma unroll
        for(int np=0;np<4;np++)
#pragma unroll
        for(int hf=0;hf<2;hf++){
            int nt=np*2+hf;
            mma_f16(acc[mt][nt], afh[mt], &bfh[np][hf*2]);
            mma_f16(acc[mt][nt], afl[mt], &bfh[np][hf*2]);
        }
        if(it+1<nst){
            buf^=1;
            *(uint4*)&sAh[buf*aoff+lr*24+lc8]       = ph0;
            *(uint4*)&sAh[buf*aoff+(lr+128)*24+lc8] = ph1;
            *(uint4*)&sAl[buf*aoff+lr*24+lc8]       = pl0;
            *(uint4*)&sAl[buf*aoff+(lr+128)*24+lc8] = pl1;
            *(uint4*)&sB [buf*boff+vbr*136+vbc]     = pb;
            __syncthreads();
        }
    }
    float* dst=g_wfull+(size_t)bh*LL*GP;
#pragma unroll
    for(int mt=0;mt<4;mt++)
#pragma unroll
    for(int nt=0;nt<8;nt++){
        int r=l0+wm*64+mt*16+(lane>>2);
        int c=j0+wn*64+nt*8+((lane&3)<<1);
        float* a4=acc[mt][nt];
        *(float2*)(dst+(size_t)r*GP+c)=make_float2(a4[0],a4[1]);
        *(float2*)(dst+(size_t)(r+8)*GP+c)=make_float2(a4[2],a4[3]);
    }
}

// ---------------------------------------------------------------------------
// Fused Toeplitz gather + cumsum + relu + mask + ROW-SUM (atomic).
// W emitted as fp16 pair; rowsums accumulated into g_rs (pre-zeroed).
// Unroll 16 for MLP (evidence: R2 u8 96us -> R7 u16 64us on same traffic).
// ---------------------------------------------------------------------------
__global__ __launch_bounds__(256) void cumsum_fuse(){
    const int bh=blockIdx.y;
    const int tid=threadIdx.x, lane=tid&31, wid=tid>>5;
    const int i=blockIdx.x*256+tid;
    const float* src=g_wfull+(size_t)bh*LL*GP+1023+i;
    __half* wh=g_Wh+(size_t)bh*LL*LL+i;
    __half* wl=g_Wl+(size_t)bh*LL*LL+i;
    __shared__ float red[16][8];
    float acc=0.f;
    for(int l=0;l<LL;l+=16){
        float vb[16];
#pragma unroll
        for(int u=0;u<16;u++) vb[u]=src[(size_t)(l+u)*2047];
        float ms[16];
#pragma unroll
        for(int u=0;u<16;u++){
            acc+=vb[u];
            float m=(i<=l+u)?fmaxf(acc,0.f):0.f;
            ms[u]=m;
            __half hh=__float2half_rn(m);
            wh[(size_t)(l+u)*LL]=hh;
            wl[(size_t)(l+u)*LL]=__float2half_rn(m-__half2float(hh));
        }
        // block row-sums for these 16 l's
#pragma unroll
        for(int u=0;u<16;u++){
            float s=ms[u];
#pragma unroll
            for(int o=16;o>0;o>>=1) s+=__shfl_xor_sync(0xffffffffu,s,o);
            if(lane==0) red[u][wid]=s;
        }
        __syncthreads();
        if(tid<16){
            float s=0.f;
#pragma unroll
            for(int w=0;w<8;w++) s+=red[tid][w];
            atomicAdd(&g_rs[bh*LL + l + tid], s);
        }
        __syncthreads();
    }
}

// ---------------------------------------------------------------------------
// AV GEMM: attn = normalize(W) @ v (causal).
// Block 256(l)x128(n), 8 warps, 64x64 warp tile, BK=16, causal K bound.
// ---------------------------------------------------------------------------
__global__ __launch_bounds__(256) void mma_av(){
    extern __shared__ __align__(16) char dsm[];
    __half* sAh = (__half*)dsm;                   // [2][256][24]
    __half* sAl = (__half*)(dsm + 24576);
    __half* sB  = (__half*)(dsm + 49152);         // [2][16][136]
    const int tid=threadIdx.x, lane=tid&31, wid=tid>>5;
    const int wm=wid>>1, wn=wid&1;
    const int bh=blockIdx.z, b=bh>>2, h=bh&3;
    const int l0=blockIdx.y*256, n0=blockIdx.x*128;

    const int lr=tid>>1, lc8=(tid&1)*8;
    const __half* Ah0=g_Wh+(size_t)(bh*LL+l0+lr)*LL+lc8;
    const __half* Ah1=g_Wh+(size_t)(bh*LL+l0+lr+128)*LL+lc8;
    const __half* Al0=g_Wl+(size_t)(bh*LL+l0+lr)*LL+lc8;
    const __half* Al1=g_Wl+(size_t)(bh*LL+l0+lr+128)*LL+lc8;
    const int vbr=tid>>4, vbc=(tid&15)<<3;
    const __half* Bp=g_vh+(size_t)(b*LL+vbr)*DD+h*DH+n0+vbc;

    float acc[4][8][4];
#pragma unroll
    for(int i=0;i<4;i++)
#pragma unroll
    for(int j=0;j<8;j++)
#pragma unroll
    for(int k2=0;k2<4;k2++) acc[i][j][k2]=0.f;

    uint4 ph0=*(const uint4*)Ah0, ph1=*(const uint4*)Ah1;
    uint4 pl0=*(const uint4*)Al0, pl1=*(const uint4*)Al1;
    uint4 pb =*(const uint4*)Bp;
    *(uint4*)&sAh[lr*24+lc8]        = ph0;
    *(uint4*)&sAh[(lr+128)*24+lc8]  = ph1;
    *(uint4*)&sAl[lr*24+lc8]        = pl0;
    *(uint4*)&sAl[(lr+128)*24+lc8]  = pl1;
    *(uint4*)&sB [vbr*136+vbc]      = pb;
    __syncthreads();

    const int nst = (l0+256)/16;
    int buf = 0;
    const int g=lane>>3;
    const int arow=((g&1)<<3)+(lane&7), acol=(g>>1)<<3;
    const int tbrow=((g&1)<<3)+(lane&7), tbcoff=(g>>1)<<3;
    const int aoff = 256*24, boff = 16*136;

    for(int it=0; it<nst; it++){
        if(it+1<nst){
            const int kb=(it+1)*16;
            ph0=*(const uint4*)(Ah0+kb); ph1=*(const uint4*)(Ah1+kb);
            pl0=*(const uint4*)(Al0+kb); pl1=*(const uint4*)(Al1+kb);
            pb =*(const uint4*)(Bp + (size_t)kb*DD);
        }
        u32 afh[4][4], afl[4][4];
#pragma unroll
        for(int mt=0;mt<4;mt++){
            ldsm4(afh[mt], smaddr(&sAh[buf*aoff+(wm*64+mt*16+arow)*24+acol]));
            ldsm4(afl[mt], smaddr(&sAl[buf*aoff+(wm*64+mt*16+arow)*24+acol]));
        }
        u32 bfh[4][4];
#pragma unroll
        for(int np=0;np<4;np++)
            ldsm4t(bfh[np], smaddr(&sB[buf*boff+tbrow*136+wn*64+np*16+tbcoff]));
#pragma unroll
        for(int mt=0;mt<4;mt++)
#pragma unroll
        for(int np=0;np<4;np++)
#pragma unroll
        for(int hf=0;hf<2;hf++){
            int nt=np*2+hf;
            mma_f16(acc[mt][nt], afh[mt], &bfh[np][hf*2]);
            mma_f16(acc[mt][nt], afl[mt], &bfh[np][hf*2]);
        }
        if(it+1<nst){
            buf^=1;
            *(uint4*)&sAh[buf*aoff+lr*24+lc8]       = ph0;
            *(uint4*)&sAh[buf*aoff+(lr+128)*24+lc8] = ph1;
            *(uint4*)&sAl[buf*aoff+lr*24+lc8]       = pl0;
            *(uint4*)&sAl[buf*aoff+(lr+128)*24+lc8] = pl1;
            *(uint4*)&sB [buf*boff+vbr*136+vbc]     = pb;
            __syncthreads();
        }
    }
#pragma unroll
    for(int mt=0;mt<4;mt++)
#pragma unroll
    for(int nt=0;nt<8;nt++){
        int r=l0+wm*64+mt*16+(lane>>2);
        int cD=h*DH+n0+wn*64+nt*8+((lane&3)<<1);
        float s0=1.f/(g_rs[bh*LL+r]+1e-8f);
        float s1=1.f/(g_rs[bh*LL+r+8]+1e-8f);
        float* a4=acc[mt][nt];
        st_pair(g_ath,g_atl,(size_t)(b*LL+r)*DD+cD,a4[0]*s0,a4[1]*s0);
        st_pair(g_ath,g_atl,(size_t)(b*LL+r+8)*DD+cD,a4[2]*s1,a4[3]*s1);
    }
}

// ---------------------------------------------------------------------------
extern "C" void kernel_launch(void* const* d_in, const int* in_sizes, int n_in,
                              void* d_out, int out_size) {
    const float* x   = (const float*)d_in[0];
    const float* gen = (const float*)d_in[1];
    const float* Wq  = (const float*)d_in[2];
    const float* Wv  = (const float*)d_in[3];
    const float* Wp  = (const float*)d_in[4];
    float* out = (float*)d_out;

    __half *xh,*xl,*wqh,*wvh,*wph,*qh,*ql,*vh,*ath,*atl;
    cudaGetSymbolAddress((void**)&xh,  g_xh);  cudaGetSymbolAddress((void**)&xl,  g_xl);
    cudaGetSymbolAddress((void**)&wqh, g_wqh);
    cudaGetSymbolAddress((void**)&wvh, g_wvh);
    cudaGetSymbolAddress((void**)&wph, g_wph);
    cudaGetSymbolAddress((void**)&qh,  g_qh);  cudaGetSymbolAddress((void**)&ql,  g_ql);
    cudaGetSymbolAddress((void**)&vh,  g_vh);
    cudaGetSymbolAddress((void**)&ath, g_ath); cudaGetSymbolAddress((void**)&atl, g_atl);

    cudaFuncSetAttribute(mma_nt2, cudaFuncAttributeMaxDynamicSharedMemorySize, NT2_SMEM);
    cudaFuncSetAttribute(mma_score, cudaFuncAttributeMaxDynamicSharedMemorySize, SC_SMEM);
    cudaFuncSetAttribute(mma_av, cudaFuncAttributeMaxDynamicSharedMemorySize, SC_SMEM);

    conv_all<<<(N_CONV+255)/256,256>>>(x, Wq, Wv, Wp, gen);
    zero_rs<<<(BB*HH*LL)/256,256>>>();

    dim3 gproj(DD/128, BB*LL/256);   // (8, 32)
    mma_nt2<<<gproj, 256, NT2_SMEM>>>(xh, xl, wqh, nullptr, qh, ql, 1);
    mma_nt2<<<gproj, 256, NT2_SMEM>>>(xh, xl, wvh, nullptr, vh, nullptr, 2);

    mma_score<<<dim3(GP/128, LL/256, BB*HH), 256, SC_SMEM>>>();
    cumsum_fuse<<<dim3(LL/256, BB*HH),256>>>();
    mma_av<<<dim3(DH/128, LL/256, BB*HH), 256, SC_SMEM>>>();

    mma_nt2<<<gproj, 256, NT2_SMEM>>>(ath, atl, wph, out, nullptr, nullptr, 0);
}